// round 7
// baseline (speedup 1.0000x reference)
#include <cuda_runtime.h>
#include <cuda_fp16.h>
#include <cstdint>

#define N_SEND 12288
#define N_REC  49152
#define NE     196608
#define DD     256
#define K1     512
#define MTOT   98304

// ---------------- static device scratch ----------------
__device__ __half d_Acc[(size_t)MTOT * K1];    // [m][512] fp16
__device__ __half d_B1[DD * K1];               // [n][512] fp16
__device__ __half d_B2[DD * DD];               // [n][256] fp16
__device__ float  d_W1cat[K1 * DD];
__device__ float  d_bc[DD];
__device__ int    d_offs[N_REC + 1];

// ---------------- gelu ----------------
__device__ __forceinline__ float gelu_mufu(float v) {
    float u = 0.7978845608028654f * fmaf(0.044715f * v, v * v, v);
    float t;
    asm("ex2.approx.f32 %0, %1;" : "=f"(t) : "f"(-2.8853900817779268f * u));
    float r;
    asm("rcp.approx.f32 %0, %1;" : "=f"(r) : "f"(1.0f + t));
    return v * r;
}
__device__ __forceinline__ float gelu_poly(float v) {
    float u = 0.7978845608028654f * fmaf(0.044715f * v, v * v, v);
    float u2 = u * u;
    float p = fmaf(u2, -0.008863235530f, 0.021869488536f);
    p = fmaf(u2, p, -0.053968253968f);
    p = fmaf(u2, p, 0.133333333333f);
    p = fmaf(u2, p, -0.333333333333f);
    float th = fmaf(u2 * u, p, u);
    float g = fmaf(0.5f * v, th, 0.5f * v);
    if (__builtin_expect(fabsf(u) > 0.65f, 0)) g = gelu_mufu(v);
    return g;
}
__device__ __forceinline__ void ldsm4(uint32_t* r, uint32_t addr) {
    asm volatile("ldmatrix.sync.aligned.m8n8.x4.shared.b16 {%0,%1,%2,%3}, [%4];"
                 : "=r"(r[0]), "=r"(r[1]), "=r"(r[2]), "=r"(r[3]) : "r"(addr));
}
__device__ __forceinline__ void mma16816(float* c, const uint32_t* a, const uint32_t* b) {
    asm volatile("mma.sync.aligned.m16n8k16.row.col.f32.f16.f16.f32 "
                 "{%0,%1,%2,%3}, {%4,%5,%6,%7}, {%8,%9}, {%0,%1,%2,%3};"
                 : "+f"(c[0]), "+f"(c[1]), "+f"(c[2]), "+f"(c[3])
                 : "r"(a[0]), "r"(a[1]), "r"(a[2]), "r"(a[3]), "r"(b[0]), "r"(b[1]));
}
#define CP_ASYNC16(s, g) asm volatile("cp.async.cg.shared.global [%0], [%1], 16;" :: "r"(s), "l"(g))
#define CP_COMMIT()      asm volatile("cp.async.commit_group;" ::: "memory")
#define CP_WAIT(n)       asm volatile("cp.async.wait_group %0;" :: "n"(n) : "memory")

// ---------------- kernel: fold We2/be2 into Wl1 ----------------
__global__ void prep_kernel(const float* __restrict__ Wl1,
                            const float* __restrict__ We2,
                            const float* __restrict__ be2) {
    int n = threadIdx.x;
    int j = blockIdx.x;
    if (j < 256) {
        d_W1cat[j * DD + n] = Wl1[j * DD + n];
        float acc = 0.f;
        #pragma unroll 4
        for (int k = 0; k < 256; k++)
            acc += We2[j * 256 + k] * Wl1[(256 + k) * DD + n];
        d_W1cat[(256 + j) * DD + n] = acc;
    } else {
        float acc = 0.f;
        #pragma unroll 4
        for (int k = 0; k < 256; k++)
            acc += be2[k] * Wl1[(256 + k) * DD + n];
        d_bc[n] = acc;
    }
}

// ---------------- pack B operands [n][k] fp16 ----------------
__global__ void pack_b1() {
    int n = threadIdx.x, k = blockIdx.x;
    d_B1[(size_t)n * K1 + k] = __float2half_rn(d_W1cat[k * DD + n]);
}
__global__ void pack_b2(const float* __restrict__ Wl2) {
    int n = threadIdx.x, k = blockIdx.x;
    d_B2[(size_t)n * DD + k] = __float2half_rn(Wl2[k * DD + n]);
}

// ---------------- segment offsets ----------------
__global__ void seg_offs_kernel(const int* __restrict__ idx_rec) {
    int e = blockIdx.x * 256 + threadIdx.x;
    if (e >= NE) return;
    int cur = idx_rec[e];
    int nxt = (e + 1 < NE) ? idx_rec[e + 1] : N_REC;
    for (int r = cur + 1; r <= nxt; r++) d_offs[r] = e + 1;
    if (e == 0) {
        for (int r = 0; r <= cur; r++) d_offs[r] = 0;
    }
}

// ---------------- fused gather + edge-MLP + segment sum (4 edge slots) ----------------
__global__ __launch_bounds__(256) void edge_kernel(const float* __restrict__ x,
                            const float* __restrict__ edge_attr,
                            const int*  __restrict__ idx_send,
                            const float* __restrict__ We1,
                            const float* __restrict__ be1) {
    __shared__ float4 sA0[4][64], sA1[4][64], sAG[4][64];
    const int r = blockIdx.x;
    const int tid = threadIdx.x;
    const int slot = tid >> 6, c = tid & 63;
    const int start = d_offs[r], end = d_offs[r + 1];

    const float4 w0 = *(const float4*)&We1[c * 4];
    const float4 w1 = *(const float4*)&We1[256 + c * 4];
    const float4 w2 = *(const float4*)&We1[512 + c * 4];
    const float4 w3 = *(const float4*)&We1[768 + c * 4];
    const float4 b0 = *(const float4*)&be1[c * 4];

    const float4* x4 = (const float4*)x;
    float4 a0 = make_float4(0.f, 0.f, 0.f, 0.f);
    float4 a1 = a0, aG = a0;

    for (int e = start + slot; e < end; e += 4) {
        int s = idx_send[e];
        float4 ea = reinterpret_cast<const float4*>(edge_attr)[e];
        float tx = b0.x + ea.x * w0.x + ea.y * w1.x + ea.z * w2.x + ea.w * w3.x;
        float ty = b0.y + ea.x * w0.y + ea.y * w1.y + ea.z * w2.y + ea.w * w3.y;
        float tz = b0.z + ea.x * w0.z + ea.y * w1.z + ea.z * w2.z + ea.w * w3.z;
        float tw = b0.w + ea.x * w0.w + ea.y * w1.w + ea.z * w2.w + ea.w * w3.w;
        aG.x += gelu_poly(tx); aG.y += gelu_poly(ty);
        aG.z += gelu_poly(tz); aG.w += gelu_poly(tw);
        float4 xv = x4[(size_t)s * 64 + c];
        a0.x += xv.x; a0.y += xv.y; a0.z += xv.z; a0.w += xv.w;
        float4 xv2 = x4[((size_t)N_SEND + s) * 64 + c];
        a1.x += xv2.x; a1.y += xv2.y; a1.z += xv2.z; a1.w += xv2.w;
    }
    sA0[slot][c] = a0; sA1[slot][c] = a1; sAG[slot][c] = aG;
    __syncthreads();

    // reduce 4 slots; 192 threads: group 0->a0, 1->a1, 2->aG
    if (tid < 192) {
        int grp = tid >> 6, cc = tid & 63;
        const float4* s4 = (grp == 0) ? sA0[0] : (grp == 1) ? sA1[0] : sAG[0];
        float4 v0 = s4[cc], v1 = s4[64 + cc], v2 = s4[128 + cc], v3 = s4[192 + cc];
        float4 v;
        v.x = v0.x + v1.x + v2.x + v3.x;
        v.y = v0.y + v1.y + v2.y + v3.y;
        v.z = v0.z + v1.z + v2.z + v3.z;
        v.w = v0.w + v1.w + v2.w + v3.w;
        __half2 h01 = __floats2half2_rn(v.x, v.y);
        __half2 h23 = __floats2half2_rn(v.z, v.w);
        uint2 u = make_uint2(*(uint32_t*)&h01, *(uint32_t*)&h23);
        size_t m0 = (size_t)r * K1;
        size_t m1 = ((size_t)N_REC + r) * K1;
        if (grp == 0) {
            *(uint2*)&d_Acc[m0 + cc * 4] = u;
        } else if (grp == 1) {
            *(uint2*)&d_Acc[m1 + cc * 4] = u;
        } else {
            *(uint2*)&d_Acc[m0 + DD + cc * 4] = u;
            *(uint2*)&d_Acc[m1 + DD + cc * 4] = u;
        }
    }
}

// ---------------- fused GEMM: (gelu(Acc@W1cat+...)) @ Wl2 + bl2, one CTA = 128x256 ----------------
#define SM_BL1  0u
#define SM_BL2  1024u
#define SM_BC   2048u
#define SM_CNT  3072u
#define SM_BUF  4096u
#define BUF_SZ  49152u
#define SM_AMID (4096u + 3u * 49152u)          // 151552
#define SMEM_TOTAL (151552 + 65536)            // 217088

template <int ROWS, int KD>
__device__ __forceinline__ void load_tile(uint32_t sdst, const __half* __restrict__ g, int tid) {
    #pragma unroll
    for (int i = 0; i < ROWS / 32; i++) {
        int lin = i * 256 + tid;
        int r = lin >> 3, c = lin & 7;
        uint32_t sa = sdst + (uint32_t)r * 128u + (uint32_t)((c ^ (r & 7)) << 4);
        CP_ASYNC16(sa, g + (size_t)r * KD + c * 8);
    }
}

__device__ __forceinline__ void mma_chunk(float* acc, uint32_t sA, uint32_t sB,
                                          int Ar0, int aSel, int Ar7,
                                          int Bn0, int bSel, int Bn7) {
    #pragma unroll
    for (int kk = 0; kk < 4; kk++) {
        uint32_t bh[16];
        #pragma unroll
        for (int p = 0; p < 4; p++) {
            uint32_t boff = (uint32_t)(Bn0 + p * 16) * 128u + (uint32_t)(((kk * 2 + bSel) ^ Bn7) << 4);
            ldsm4(&bh[p * 4], sB + boff);
        }
        #pragma unroll
        for (int t = 0; t < 4; t++) {
            uint32_t aoff = (uint32_t)(Ar0 + t * 16) * 128u + (uint32_t)(((kk * 2 + aSel) ^ Ar7) << 4);
            uint32_t ah[4];
            ldsm4(ah, sA + aoff);
            #pragma unroll
            for (int n = 0; n < 8; n++) {
                mma16816(&acc[(t * 8 + n) * 4], ah, &bh[(n >> 1) * 4 + (n & 1) * 2]);
            }
        }
    }
}

__global__ __launch_bounds__(256, 1) void gemm_fused(const float* __restrict__ bl1,
                                                     const float* __restrict__ bl2,
                                                     float* __restrict__ outp) {
    extern __shared__ char smem[];
    const uint32_t sb = (uint32_t)__cvta_generic_to_shared(smem);
    const int tid = threadIdx.x;
    const int tileM = blockIdx.x;
    const int wid = tid >> 5, lane = tid & 31;
    const int wm = (wid >> 2) * 64, wn = (wid & 3) * 64;

    // misc smem
    ((float*)(smem + SM_BL1))[tid & 255] = bl1[tid & 255];
    ((float*)(smem + SM_BL2))[tid & 255] = bl2[tid & 255];
    ((float*)(smem + SM_BC))[tid & 255]  = d_bc[tid & 255];
    if (tid < 128) {
        int R = tileM * 128 + tid;
        int rr = (R >= N_REC) ? R - N_REC : R;
        ((float*)(smem + SM_CNT))[tid] = (float)(d_offs[rr + 1] - d_offs[rr]);
    }

    const size_t Abase = (size_t)tileM * 128 * K1;

    #define LOAD1(c, buf) do {                                               \
        uint32_t s_ = sb + SM_BUF + (uint32_t)(buf) * BUF_SZ;                \
        load_tile<128, K1>(s_,          d_Acc + Abase + (c) * 64, tid);      \
        load_tile<256, K1>(s_ + 16384u, d_B1 + (c) * 64, tid);               \
        CP_COMMIT();                                                         \
    } while (0)
    #define LOADB2(c, buf) do {                                              \
        uint32_t s_ = sb + SM_BUF + (uint32_t)(buf) * BUF_SZ;                \
        load_tile<256, DD>(s_ + 16384u, d_B2 + (c) * 64, tid);               \
        CP_COMMIT();                                                         \
    } while (0)

    LOAD1(0, 0); LOAD1(1, 1); LOAD1(2, 2);

    const int sub = lane >> 3, rr8 = lane & 7;
    const int Ar0 = wm + ((sub & 1) << 3) + rr8;
    const int aSel = sub >> 1;
    const int Ar7 = Ar0 & 7;
    const int Bn0 = wn + ((sub >> 1) << 3) + rr8;
    const int bSel = sub & 1;
    const int Bn7 = Bn0 & 7;
    const int gid = lane >> 2, qid = lane & 3;

    float acc[128];
    #pragma unroll
    for (int i = 0; i < 128; i++) acc[i] = 0.f;

    // ---------------- GEMM1: Acc[128x512] @ B1^T -> 128x256 ----------------
    #pragma unroll
    for (int c = 0; c < 8; c++) {
        if (7 - c >= 2)      { CP_WAIT(2); }
        else if (7 - c == 1) { CP_WAIT(1); }
        else                 { CP_WAIT(0); }
        __syncthreads();
        const uint32_t sB0 = sb + SM_BUF + (uint32_t)(c % 3) * BUF_SZ;
        mma_chunk(acc, sB0, sB0 + 16384u, Ar0, aSel, Ar7, Bn0, bSel, Bn7);
        __syncthreads();
        if (c + 3 < 8) LOAD1(c + 3, (c + 3) % 3);
    }

    // prefetch B2 chunks (overlaps with epilogue1)
    LOADB2(0, 0); LOADB2(1, 1); LOADB2(2, 2);

    // ---------------- epilogue1: gelu -> smem Amid (swizzled fp16 chunks) ----------------
    {
        const float* sbl1 = (const float*)(smem + SM_BL1);
        const float* sbc  = (const float*)(smem + SM_BC);
        const float* scnt = (const float*)(smem + SM_CNT);
        #pragma unroll
        for (int t = 0; t < 4; t++) {
            #pragma unroll
            for (int n = 0; n < 8; n++) {
                float* a4 = &acc[(t * 8 + n) * 4];
                int rl = wm + t * 16 + gid;
                int cl = wn + n * 8 + qid * 2;
                float b0 = sbl1[cl], b1 = sbl1[cl + 1];
                float bc0 = sbc[cl], bc1 = sbc[cl + 1];
                float cf0 = scnt[rl], cf1 = scnt[rl + 8];
                float v00 = gelu_mufu(a4[0] + b0 + cf0 * bc0);
                float v01 = gelu_mufu(a4[1] + b1 + cf0 * bc1);
                float v10 = gelu_mufu(a4[2] + b0 + cf1 * bc0);
                float v11 = gelu_mufu(a4[3] + b1 + cf1 * bc1);
                int chunk = cl >> 6, cc = cl & 63;
                int g = cc >> 3;
                uint32_t base = SM_AMID + (uint32_t)chunk * 16384u + (uint32_t)(cc & 7) * 2u;
                __half2 h0 = __floats2half2_rn(v00, v01);
                __half2 h1 = __floats2half2_rn(v10, v11);
                *(uint32_t*)(smem + base + (uint32_t)rl * 128u + (uint32_t)((g ^ (rl & 7)) << 4)) = *(uint32_t*)&h0;
                *(uint32_t*)(smem + base + (uint32_t)(rl + 8) * 128u + (uint32_t)((g ^ ((rl + 8) & 7)) << 4)) = *(uint32_t*)&h1;
            }
        }
    }
    #pragma unroll
    for (int i = 0; i < 128; i++) acc[i] = 0.f;

    // ---------------- GEMM2: Amid[128x256](smem) @ B2^T -> 128x256 ----------------
    #pragma unroll
    for (int c = 0; c < 4; c++) {
        if (3 - c >= 2)      { CP_WAIT(2); }
        else if (3 - c == 1) { CP_WAIT(1); }
        else                 { CP_WAIT(0); }
        __syncthreads();
        const uint32_t sA2 = sb + SM_AMID + (uint32_t)c * 16384u;
        const uint32_t sB2 = sb + SM_BUF + (uint32_t)(c % 3) * BUF_SZ + 16384u;
        mma_chunk(acc, sA2, sB2, Ar0, aSel, Ar7, Bn0, bSel, Bn7);
        __syncthreads();
        if (c + 3 < 4) LOADB2(c + 3, (c + 3) % 3);
    }
    #undef LOAD1
    #undef LOADB2

    // ---------------- final epilogue ----------------
    const float* sbl2 = (const float*)(smem + SM_BL2);
    #pragma unroll
    for (int t = 0; t < 4; t++) {
        #pragma unroll
        for (int n = 0; n < 8; n++) {
            float* a4 = &acc[(t * 8 + n) * 4];
            int rl = wm + t * 16 + gid;
            int cl = wn + n * 8 + qid * 2;
            int Rg = tileM * 128 + rl;
            float b0 = sbl2[cl], b1 = sbl2[cl + 1];
            *(float2*)&outp[(size_t)Rg * DD + cl] = make_float2(a4[0] + b0, a4[1] + b1);
            *(float2*)&outp[(size_t)(Rg + 8) * DD + cl] = make_float2(a4[2] + b0, a4[3] + b1);
        }
    }
}

// ---------------- launch ----------------
extern "C" void kernel_launch(void* const* d_in, const int* in_sizes, int n_in,
                              void* d_out, int out_size) {
    const float* x         = (const float*)d_in[0];
    const float* edge_attr = (const float*)d_in[1];
    const int*   idx_send  = (const int*)d_in[2];
    const int*   idx_rec   = (const int*)d_in[3];
    const float* We1       = (const float*)d_in[4];
    const float* be1       = (const float*)d_in[5];
    const float* We2       = (const float*)d_in[6];
    const float* be2       = (const float*)d_in[7];
    const float* Wl1       = (const float*)d_in[8];
    const float* bl1       = (const float*)d_in[9];
    const float* Wl2       = (const float*)d_in[10];
    const float* bl2       = (const float*)d_in[11];
    float* out = (float*)d_out;

    static bool attr_done = false;
    if (!attr_done) {
        cudaFuncSetAttribute(gemm_fused, cudaFuncAttributeMaxDynamicSharedMemorySize, SMEM_TOTAL);
        attr_done = true;
    }

    prep_kernel<<<257, 256>>>(Wl1, We2, be2);
    pack_b1<<<K1, 256>>>();
    pack_b2<<<DD, 256>>>(Wl2);
    seg_offs_kernel<<<(NE + 255) / 256, 256>>>(idx_rec);
    edge_kernel<<<N_REC, 256>>>(x, edge_attr, idx_send, We1, be1);

    gemm_fused<<<MTOT / 128, 256, SMEM_TOTAL>>>(bl1, bl2, out);
}